// round 5
// baseline (speedup 1.0000x reference)
#include <cuda_runtime.h>
#include <math.h>

#define N_NODES 50000
#define N_EDGES 800000
#define HID 64
#define SCAN_BLOCKS 128

// ---------------- scratch (device globals) ----------------
__device__ float g_h[N_NODES*HID];
__device__ float g_feat[N_NODES*HID];
__device__ float g_fcat[N_NODES*4*HID];
__device__ float g_el[N_NODES];
__device__ float g_er[N_NODES];
__device__ float g_aexp[N_EDGES];         // only used by the rare deg>32 path
__device__ unsigned char g_mask[N_EDGES];
__device__ int g_deg[N_NODES];
__device__ int g_off[N_NODES+1];
__device__ int g_rank[N_EDGES];
__device__ int g_csr_src[N_EDGES];
__device__ int g_bsum[SCAN_BLOCKS];

// ---------------- packed f32x2 helpers ----------------
__device__ __forceinline__ unsigned long long ffma2(unsigned long long a,
                                                    unsigned long long b,
                                                    unsigned long long c){
  unsigned long long d;
  asm("fma.rn.f32x2 %0, %1, %2, %3;" : "=l"(d) : "l"(a), "l"(b), "l"(c));
  return d;
}
__device__ __forceinline__ unsigned long long packff(float x){
  unsigned long long u;
  asm("mov.b64 %0, {%1, %1};" : "=l"(u) : "f"(x));
  return u;
}
__device__ __forceinline__ float2 unpackff(unsigned long long u){
  float2 f;
  asm("mov.b64 {%0, %1}, %2;" : "=f"(f.x), "=f"(f.y) : "l"(u));
  return f;
}

// ---------------- register-tiled GEMM, 128 threads, thread tile 32r x 2c ----------------
// C[n,64] = act(A[n,K] @ W[K,64] (+bias)); ACT: 0=none, 1=tanh, 2=bias+relu
template<int K, int ACT>
__global__ void gemm2_k(const float* __restrict__ A, const float* __restrict__ W,
                        const float* __restrict__ bias, float* __restrict__ out, int n)
{
  __shared__ float As[64][128];   // transposed A chunk, swizzled
  __shared__ float Ws[64][64];
  int tid = threadIdx.x;          // 0..127
  int c0 = tid & 31, rb = tid >> 5;   // rb 0..3 -> rows rb*32..rb*32+31
  int row0 = blockIdx.x * 128;

  unsigned long long acc[16][2];
  #pragma unroll
  for (int p = 0; p < 16; ++p) { acc[p][0] = 0ull; acc[p][1] = 0ull; }

  for (int kc = 0; kc < K; kc += 64) {
    __syncthreads();
    // A chunk (coalesced) -> transposed smem with swizzle
    #pragma unroll
    for (int j = 0; j < 16; ++j) {
      int idx = tid + 128*j;            // 2048 float4 slots
      int r  = idx >> 4;                // 0..127
      int k0 = (idx & 15) * 4;          // 0..60
      float4 v = make_float4(0.f,0.f,0.f,0.f);
      int grow = row0 + r;
      if (grow < n) v = *(const float4*)(A + (size_t)grow*K + kc + k0);
      int rs = r ^ (4*((k0 >> 2) & 7));
      As[k0+0][rs] = v.x; As[k0+1][rs] = v.y;
      As[k0+2][rs] = v.z; As[k0+3][rs] = v.w;
    }
    // W chunk (straight copy)
    #pragma unroll
    for (int j = 0; j < 8; ++j) {
      int idx = tid + 128*j;            // 1024 float4 slots
      int kr = idx >> 4, cq = (idx & 15) * 4;
      *(float4*)&Ws[kr][cq] = *(const float4*)(W + (size_t)(kc+kr)*64 + cq);
    }
    __syncthreads();

    #pragma unroll 2
    for (int k = 0; k < 64; ++k) {
      unsigned long long w0 = packff(Ws[k][c0]);
      unsigned long long w1 = packff(Ws[k][c0+32]);
      int v = 4*((k >> 2) & 7);
      #pragma unroll
      for (int u = 0; u < 8; ++u) {
        int rr = (rb*32 + 4*u) ^ v;
        ulonglong2 av = *(const ulonglong2*)&As[k][rr];
        acc[2*u  ][0] = ffma2(av.x, w0, acc[2*u  ][0]);
        acc[2*u  ][1] = ffma2(av.x, w1, acc[2*u  ][1]);
        acc[2*u+1][0] = ffma2(av.y, w0, acc[2*u+1][0]);
        acc[2*u+1][1] = ffma2(av.y, w1, acc[2*u+1][1]);
      }
    }
  }

  float b0v = 0.f, b1v = 0.f;
  if (ACT == 2) { b0v = bias[c0]; b1v = bias[c0+32]; }
  #pragma unroll
  for (int p = 0; p < 16; ++p) {
    int r = row0 + rb*32 + 2*p;
    float2 va = unpackff(acc[p][0]);
    float2 vb = unpackff(acc[p][1]);
    float o00 = va.x, o01 = vb.x, o10 = va.y, o11 = vb.y;
    if (ACT == 1) { o00 = tanhf(o00); o01 = tanhf(o01); o10 = tanhf(o10); o11 = tanhf(o11); }
    if (ACT == 2) {
      o00 = fmaxf(o00 + b0v, 0.f); o01 = fmaxf(o01 + b1v, 0.f);
      o10 = fmaxf(o10 + b0v, 0.f); o11 = fmaxf(o11 + b1v, 0.f);
    }
    if (r < n)     { out[(size_t)r*64 + c0] = o00;     out[(size_t)r*64 + c0 + 32] = o01; }
    if (r + 1 < n) { out[(size_t)(r+1)*64 + c0] = o10; out[(size_t)(r+1)*64 + c0 + 32] = o11; }
  }
}

// ---------------- el/er ----------------
__global__ void eler_k(const float* __restrict__ al, const float* __restrict__ ar, int n){
  int tid = threadIdx.x, lane = tid & 31, warp = tid >> 5;
  int row = blockIdx.x * 8 + warp;
  if (row >= n) return;
  float f0 = g_feat[(size_t)row*64 + lane];
  float f1 = g_feat[(size_t)row*64 + 32 + lane];
  float pl = f0*al[lane] + f1*al[lane+32];
  float pr = f0*ar[lane] + f1*ar[lane+32];
  #pragma unroll
  for (int o = 16; o; o >>= 1) {
    pl += __shfl_xor_sync(0xffffffffu, pl, o);
    pr += __shfl_xor_sync(0xffffffffu, pr, o);
  }
  if (lane == 0) { g_el[row] = pl; g_er[row] = pr; }
}

// ---------------- CSR build ----------------
__global__ void zero_deg_k(int n){
  int i = blockIdx.x*blockDim.x + threadIdx.x;
  if (i < n) g_deg[i] = 0;
}
// histogram; keep the atomicAdd return as the edge's rank within its dst bucket
__global__ void hist_k(const int* __restrict__ dst, int e){
  int i = 4*(blockIdx.x*blockDim.x + threadIdx.x);
  if (i + 4 <= e) {
    int4 d = *(const int4*)(dst + i);
    int4 r;
    r.x = atomicAdd(&g_deg[d.x], 1);
    r.y = atomicAdd(&g_deg[d.y], 1);
    r.z = atomicAdd(&g_deg[d.z], 1);
    r.w = atomicAdd(&g_deg[d.w], 1);
    *(int4*)(g_rank + i) = r;
  } else {
    for (int j = i; j < e; ++j) g_rank[j] = atomicAdd(&g_deg[dst[j]], 1);
  }
}
__global__ void scan1_k(int n){
  __shared__ int ss[256];
  int per = (n + SCAN_BLOCKS - 1) / SCAN_BLOCKS;
  int b0 = blockIdx.x*per, b1 = min(b0+per, n);
  int s = 0;
  for (int i = b0 + threadIdx.x; i < b1; i += 256) s += g_deg[i];
  ss[threadIdx.x] = s;
  __syncthreads();
  for (int o = 128; o; o >>= 1) {
    if (threadIdx.x < o) ss[threadIdx.x] += ss[threadIdx.x + o];
    __syncthreads();
  }
  if (threadIdx.x == 0) g_bsum[blockIdx.x] = ss[0];
}
// scan3 also absorbs the cross-block prefix (redundant 128-element sum per block)
__global__ void scan3_k(int n, int e){
  __shared__ int ss[256];
  // exclusive prefix of g_bsum[0..blockIdx.x)
  int part = 0;
  for (int i = threadIdx.x; i < blockIdx.x; i += 256) part += g_bsum[i];
  ss[threadIdx.x] = part;
  __syncthreads();
  for (int o = 128; o; o >>= 1) {
    if (threadIdx.x < o) ss[threadIdx.x] += ss[threadIdx.x + o];
    __syncthreads();
  }
  int base = ss[0];
  __syncthreads();

  int per = (n + SCAN_BLOCKS - 1) / SCAN_BLOCKS;
  int b0 = blockIdx.x*per, b1 = min(b0+per, n);
  int len = b1 - b0;
  int chunk = (len + 255) / 256;
  int t0 = b0 + threadIdx.x*chunk, t1 = min(t0 + chunk, b1);
  int s = 0;
  for (int i = t0; i < t1; ++i) s += g_deg[i];
  ss[threadIdx.x] = s;
  __syncthreads();
  for (int d = 1; d < 256; d <<= 1) {
    int t = (threadIdx.x >= d) ? ss[threadIdx.x-d] : 0;
    __syncthreads();
    ss[threadIdx.x] += t;
    __syncthreads();
  }
  int off = base + ss[threadIdx.x] - s;
  for (int i = t0; i < t1; ++i) { g_off[i] = off; off += g_deg[i]; }
  if (blockIdx.x == 0 && threadIdx.x == 0) g_off[n] = e;
}
// atomic-free scatter using precomputed ranks
__global__ void scatter2_k(const int* __restrict__ src, const int* __restrict__ dst, int e){
  int i = 4*(blockIdx.x*blockDim.x + threadIdx.x);
  if (i + 4 <= e) {
    int4 d = *(const int4*)(dst + i);
    int4 s = *(const int4*)(src + i);
    int4 r = *(const int4*)(g_rank + i);
    g_csr_src[g_off[d.x] + r.x] = s.x;
    g_csr_src[g_off[d.y] + r.y] = s.y;
    g_csr_src[g_off[d.z] + r.z] = s.z;
    g_csr_src[g_off[d.w] + r.w] = s.w;
  } else {
    for (int j = i; j < e; ++j) g_csr_src[g_off[dst[j]] + g_rank[j]] = src[j];
  }
}

// ---------------- fused per-layer edge kernel ----------------
__global__ void agg_k(int n, int layer){
  int tid = threadIdx.x, lane = tid & 31, warp = tid >> 5;
  int node = blockIdx.x * 8 + warp;
  if (node >= n) return;
  int beg = g_off[node], end = g_off[node+1];
  int deg = end - beg;
  float erd = g_er[node];

  if (deg <= 32) {
    int s = 0; float v = -1e30f;
    if (lane < deg) {
      s = g_csr_src[beg + lane];
      v = g_el[s] + erd;
      v = (v >= 0.f) ? v : 0.2f*v;
      if (layer > 0 && !g_mask[beg + lane]) v = -1e9f;
    }
    float m = v;
    #pragma unroll
    for (int o = 16; o; o >>= 1) m = fmaxf(m, __shfl_xor_sync(0xffffffffu, m, o));
    float a = (lane < deg) ? expf(v - m) : 0.f;
    float se = a;
    #pragma unroll
    for (int o = 16; o; o >>= 1) se += __shfl_xor_sync(0xffffffffu, se, o);
    float alpha = a / fmaxf(se, 1e-9f);
    if (layer == 0 && lane < deg) g_mask[beg + lane] = (alpha >= 0.01f) ? 1 : 0;
    if (alpha == 0.f) s = 0;

    int half = lane >> 4, q = lane & 15;
    const float* fb = g_feat + q*4;
    float4 acc = make_float4(0.f, 0.f, 0.f, 0.f);
    int npair = (deg + 1) >> 1;
    int p = 0;
    for (; p + 4 <= npair; p += 4) {
      int j0 = 2*p + half, j1 = j0 + 2, j2 = j0 + 4, j3 = j0 + 6;
      int s0 = __shfl_sync(0xffffffffu, s, j0);
      int s1 = __shfl_sync(0xffffffffu, s, j1);
      int s2 = __shfl_sync(0xffffffffu, s, j2);
      int s3 = __shfl_sync(0xffffffffu, s, j3);
      float a0 = __shfl_sync(0xffffffffu, alpha, j0);
      float a1 = __shfl_sync(0xffffffffu, alpha, j1);
      float a2 = __shfl_sync(0xffffffffu, alpha, j2);
      float a3 = __shfl_sync(0xffffffffu, alpha, j3);
      float4 f0 = *(const float4*)(fb + (size_t)s0*64);
      float4 f1 = *(const float4*)(fb + (size_t)s1*64);
      float4 f2 = *(const float4*)(fb + (size_t)s2*64);
      float4 f3 = *(const float4*)(fb + (size_t)s3*64);
      acc.x = fmaf(a0, f0.x, acc.x); acc.y = fmaf(a0, f0.y, acc.y);
      acc.z = fmaf(a0, f0.z, acc.z); acc.w = fmaf(a0, f0.w, acc.w);
      acc.x = fmaf(a1, f1.x, acc.x); acc.y = fmaf(a1, f1.y, acc.y);
      acc.z = fmaf(a1, f1.z, acc.z); acc.w = fmaf(a1, f1.w, acc.w);
      acc.x = fmaf(a2, f2.x, acc.x); acc.y = fmaf(a2, f2.y, acc.y);
      acc.z = fmaf(a2, f2.z, acc.z); acc.w = fmaf(a2, f2.w, acc.w);
      acc.x = fmaf(a3, f3.x, acc.x); acc.y = fmaf(a3, f3.y, acc.y);
      acc.z = fmaf(a3, f3.z, acc.z); acc.w = fmaf(a3, f3.w, acc.w);
    }
    for (; p < npair; ++p) {
      int j = 2*p + half;
      int sj = __shfl_sync(0xffffffffu, s, j);
      float aj = __shfl_sync(0xffffffffu, alpha, j);
      float4 f = *(const float4*)(fb + (size_t)sj*64);
      acc.x = fmaf(aj, f.x, acc.x); acc.y = fmaf(aj, f.y, acc.y);
      acc.z = fmaf(aj, f.z, acc.z); acc.w = fmaf(aj, f.w, acc.w);
    }
    acc.x += __shfl_xor_sync(0xffffffffu, acc.x, 16);
    acc.y += __shfl_xor_sync(0xffffffffu, acc.y, 16);
    acc.z += __shfl_xor_sync(0xffffffffu, acc.z, 16);
    acc.w += __shfl_xor_sync(0xffffffffu, acc.w, 16);
    if (half == 0) {
      float4 o;
      o.x = (acc.x > 0.f) ? acc.x : expm1f(acc.x);
      o.y = (acc.y > 0.f) ? acc.y : expm1f(acc.y);
      o.z = (acc.z > 0.f) ? acc.z : expm1f(acc.z);
      o.w = (acc.w > 0.f) ? acc.w : expm1f(acc.w);
      *(float4*)(g_h    + (size_t)node*64  + q*4) = o;
      *(float4*)(g_fcat + (size_t)node*256 + layer*64 + q*4) = o;
    }
  } else {
    float m = -1e30f;
    for (int j = beg + lane; j < end; j += 32) {
      int s = g_csr_src[j];
      float v = g_el[s] + erd;
      v = (v >= 0.f) ? v : 0.2f*v;
      if (layer > 0 && !g_mask[j]) v = -1e9f;
      g_aexp[j] = v;
      m = fmaxf(m, v);
    }
    #pragma unroll
    for (int o = 16; o; o >>= 1) m = fmaxf(m, __shfl_xor_sync(0xffffffffu, m, o));
    float se = 0.f;
    for (int j = beg + lane; j < end; j += 32) {
      float a = expf(g_aexp[j] - m);
      g_aexp[j] = a;
      se += a;
    }
    #pragma unroll
    for (int o = 16; o; o >>= 1) se += __shfl_xor_sync(0xffffffffu, se, o);
    float inv = 1.f / fmaxf(se, 1e-9f);
    __syncwarp();
    if (layer == 0) {
      for (int j = beg + lane; j < end; j += 32)
        g_mask[j] = (g_aexp[j]*inv >= 0.01f) ? 1 : 0;
    }
    float acc0 = 0.f, acc1 = 0.f;
    int j = beg;
    for (; j + 4 <= end; j += 4) {
      int s0 = g_csr_src[j], s1 = g_csr_src[j+1], s2 = g_csr_src[j+2], s3 = g_csr_src[j+3];
      float a0 = g_aexp[j]*inv,   a1 = g_aexp[j+1]*inv;
      float a2 = g_aexp[j+2]*inv, a3 = g_aexp[j+3]*inv;
      float2 f0 = *(const float2*)(g_feat + (size_t)s0*64 + 2*lane);
      float2 f1 = *(const float2*)(g_feat + (size_t)s1*64 + 2*lane);
      float2 f2 = *(const float2*)(g_feat + (size_t)s2*64 + 2*lane);
      float2 f3 = *(const float2*)(g_feat + (size_t)s3*64 + 2*lane);
      acc0 = fmaf(a0, f0.x, acc0); acc1 = fmaf(a0, f0.y, acc1);
      acc0 = fmaf(a1, f1.x, acc0); acc1 = fmaf(a1, f1.y, acc1);
      acc0 = fmaf(a2, f2.x, acc0); acc1 = fmaf(a2, f2.y, acc1);
      acc0 = fmaf(a3, f3.x, acc0); acc1 = fmaf(a3, f3.y, acc1);
    }
    for (; j < end; ++j) {
      int s = g_csr_src[j];
      float a = g_aexp[j]*inv;
      float2 f = *(const float2*)(g_feat + (size_t)s*64 + 2*lane);
      acc0 = fmaf(a, f.x, acc0); acc1 = fmaf(a, f.y, acc1);
    }
    float o0 = (acc0 > 0.f) ? acc0 : expm1f(acc0);
    float o1 = (acc1 > 0.f) ? acc1 : expm1f(acc1);
    g_h[(size_t)node*64 + 2*lane]     = o0;
    g_h[(size_t)node*64 + 2*lane + 1] = o1;
    g_fcat[(size_t)node*256 + layer*64 + 2*lane]     = o0;
    g_fcat[(size_t)node*256 + layer*64 + 2*lane + 1] = o1;
  }
}

// ---------------- final 64 -> 1 layer ----------------
__global__ void mlp2_k(const float* __restrict__ T, const float* __restrict__ W2,
                       const float* __restrict__ b2, float* __restrict__ out, int n){
  int tid = threadIdx.x, lane = tid & 31, warp = tid >> 5;
  int row = blockIdx.x * 8 + warp;
  if (row >= n) return;
  float s = T[(size_t)row*64 + lane]*W2[lane] + T[(size_t)row*64 + 32 + lane]*W2[lane+32];
  #pragma unroll
  for (int o = 16; o; o >>= 1) s += __shfl_xor_sync(0xffffffffu, s, o);
  if (lane == 0) out[row] = fmaxf(s + b2[0], 0.f);
}

// ---------------- launch ----------------
extern "C" void kernel_launch(void* const* d_in, const int* in_sizes, int n_in,
                              void* d_out, int out_size)
{
  const float* x       = (const float*)d_in[0];
  const int*   esrc    = (const int*)  d_in[1];
  const int*   edst    = (const int*)  d_in[2];
  const float* W_embed = (const float*)d_in[3];
  const float* W_gat   = (const float*)d_in[4];
  const float* a_l     = (const float*)d_in[5];
  const float* a_r     = (const float*)d_in[6];
  const float* W0      = (const float*)d_in[7];
  const float* b0      = (const float*)d_in[8];
  const float* W1      = (const float*)d_in[9];
  const float* b1      = (const float*)d_in[10];
  const float* W2      = (const float*)d_in[11];
  const float* b2      = (const float*)d_in[12];
  float* out = (float*)d_out;

  int n = in_sizes[0] / 128;
  int e = in_sizes[1];

  float *h_ptr, *feat_ptr, *fcat_ptr;
  cudaGetSymbolAddress((void**)&h_ptr,    g_h);
  cudaGetSymbolAddress((void**)&feat_ptr, g_feat);
  cudaGetSymbolAddress((void**)&fcat_ptr, g_fcat);

  int tiles = (n + 127) / 128;
  int gW = (n + 7) / 8;

  // CSR build (atomic-free scatter via ranks)
  zero_deg_k<<<(n + 255)/256, 256>>>(n);
  hist_k<<<((e+3)/4 + 255)/256, 256>>>(edst, e);
  scan1_k<<<SCAN_BLOCKS, 256>>>(n);
  scan3_k<<<SCAN_BLOCKS, 256>>>(n, e);
  scatter2_k<<<((e+3)/4 + 255)/256, 256>>>(esrc, edst, e);

  // embed
  gemm2_k<128, 1><<<tiles, 128>>>(x, W_embed, nullptr, h_ptr, n);

  for (int l = 0; l < 4; ++l) {
    gemm2_k<64, 0><<<tiles, 128>>>(h_ptr, W_gat + l*64*64, nullptr, feat_ptr, n);
    eler_k<<<gW, 256>>>(a_l + l*64, a_r + l*64, n);
    agg_k<<<gW, 256>>>(n, l);
  }

  // MLP head
  gemm2_k<256, 2><<<tiles, 128>>>(fcat_ptr, W0, b0, feat_ptr, n);
  gemm2_k<64,  2><<<tiles, 128>>>(feat_ptr, W1, b1, h_ptr, n);
  mlp2_k<<<gW, 256>>>(h_ptr, W2, b2, out, n);
}

// round 6
// speedup vs baseline: 1.1249x; 1.1249x over previous
#include <cuda_runtime.h>
#include <math.h>

#define N_NODES 50000
#define N_EDGES 800000
#define HID 64
#define SCAN_BLOCKS 128

// ---------------- scratch (device globals) ----------------
__device__ float g_h[N_NODES*HID];
__device__ float g_feat[N_NODES*HID];
__device__ float g_fcat[N_NODES*4*HID];
__device__ float g_el[N_NODES];
__device__ float g_er[N_NODES];
__device__ float g_aexp[N_EDGES];         // only used by the rare deg>32 path
__device__ unsigned char g_mask[N_EDGES];
__device__ int g_deg[N_NODES];
__device__ int g_off[N_NODES+1];
__device__ int g_rank[N_EDGES];
__device__ int g_csr_src[N_EDGES];
__device__ int g_bsum[SCAN_BLOCKS];

// ---------------- packed f32x2 helpers ----------------
__device__ __forceinline__ unsigned long long ffma2(unsigned long long a,
                                                    unsigned long long b,
                                                    unsigned long long c){
  unsigned long long d;
  asm("fma.rn.f32x2 %0, %1, %2, %3;" : "=l"(d) : "l"(a), "l"(b), "l"(c));
  return d;
}
__device__ __forceinline__ float2 unpackff(unsigned long long u){
  float2 f;
  asm("mov.b64 {%0, %1}, %2;" : "=f"(f.x), "=f"(f.y) : "l"(u));
  return f;
}

// ---------------- k-pair-packed GEMM: C[n,64] = act(A[n,K] @ W[K,64]) ----------------
// 256 threads; tile 128 rows x 64 cols; thread tile 8 rows x 4 cols.
// f32x2 lanes = (even k, odd k); epilogue folds .x+.y.
// As[r][k] plain rows (u64 = contiguous k-pair); k-index XOR 2*(rg&1) for banks.
// Wt[c][k] transposed W; k-index XOR 2*cg -> 16 distinct banks, conflict-free.
// ACT: 0=none, 1=tanh, 2=bias+relu
template<int K, int ACT>
__global__ void __launch_bounds__(256) gemm4_k(const float* __restrict__ A,
                        const float* __restrict__ W,
                        const float* __restrict__ bias, float* __restrict__ out, int n)
{
  __shared__ float As[128*64];
  __shared__ float Wt[64*64];
  int tid = threadIdx.x;
  int cg = tid & 15;            // cols cg*4 .. cg*4+3
  int rg = tid >> 4;            // rows rg*8 .. rg*8+7
  int row0 = blockIdx.x * 128;
  int mW = 2*cg;                // W bank swizzle mask (even)
  int mA = (rg & 1) << 1;       // A bank swizzle mask (0 or 2)

  unsigned long long acc[8][4];
  #pragma unroll
  for (int i = 0; i < 8; ++i)
    #pragma unroll
    for (int j = 0; j < 4; ++j) acc[i][j] = 0ull;

  for (int kc = 0; kc < K; kc += 64) {
    __syncthreads();
    // A fill: 128 rows x 64 k = 2048 float4; swizzle = swap float4 halves on odd rg
    #pragma unroll
    for (int j = 0; j < 8; ++j) {
      int idx = tid + 256*j;
      int r = idx >> 4, k0 = (idx & 15) * 4;
      float4 v = make_float4(0.f,0.f,0.f,0.f);
      int gr = row0 + r;
      if (gr < n) v = *(const float4*)(A + (size_t)gr*K + kc + k0);
      float4 s = ((r >> 3) & 1) ? make_float4(v.z, v.w, v.x, v.y) : v;
      *(float4*)&As[r*64 + k0] = s;
    }
    // W fill: transpose + swizzle (coalesced read)
    #pragma unroll
    for (int j = 0; j < 16; ++j) {
      int idx = tid + 256*j;
      int kr = idx >> 6;        // 0..63
      int c  = idx & 63;
      Wt[c*64 + (kr ^ (2*((c >> 2) & 15)))] = W[(size_t)(kc+kr)*64 + c];
    }
    __syncthreads();

    #pragma unroll 4
    for (int kp = 0; kp < 32; ++kp) {
      int k2 = 2*kp;
      unsigned long long a[8];
      #pragma unroll
      for (int i = 0; i < 8; ++i)
        a[i] = *(const unsigned long long*)&As[(rg*8+i)*64 + (k2 ^ mA)];
      unsigned long long w[4];
      #pragma unroll
      for (int j = 0; j < 4; ++j)
        w[j] = *(const unsigned long long*)&Wt[(cg*4+j)*64 + (k2 ^ mW)];
      #pragma unroll
      for (int i = 0; i < 8; ++i)
        #pragma unroll
        for (int j = 0; j < 4; ++j)
          acc[i][j] = ffma2(a[i], w[j], acc[i][j]);
    }
  }

  float4 bv = make_float4(0.f,0.f,0.f,0.f);
  if (ACT == 2) bv = *(const float4*)(bias + cg*4);
  #pragma unroll
  for (int i = 0; i < 8; ++i) {
    int r = row0 + rg*8 + i;
    if (r < n) {
      float2 t0 = unpackff(acc[i][0]);
      float2 t1 = unpackff(acc[i][1]);
      float2 t2 = unpackff(acc[i][2]);
      float2 t3 = unpackff(acc[i][3]);
      float4 o = make_float4(t0.x+t0.y, t1.x+t1.y, t2.x+t2.y, t3.x+t3.y);
      if (ACT == 1) { o.x = tanhf(o.x); o.y = tanhf(o.y); o.z = tanhf(o.z); o.w = tanhf(o.w); }
      if (ACT == 2) {
        o.x = fmaxf(o.x + bv.x, 0.f); o.y = fmaxf(o.y + bv.y, 0.f);
        o.z = fmaxf(o.z + bv.z, 0.f); o.w = fmaxf(o.w + bv.w, 0.f);
      }
      *(float4*)(out + (size_t)r*64 + cg*4) = o;
    }
  }
}

// ---------------- el/er ----------------
__global__ void eler_k(const float* __restrict__ al, const float* __restrict__ ar, int n){
  int tid = threadIdx.x, lane = tid & 31, warp = tid >> 5;
  int row = blockIdx.x * 8 + warp;
  if (row >= n) return;
  float f0 = g_feat[(size_t)row*64 + lane];
  float f1 = g_feat[(size_t)row*64 + 32 + lane];
  float pl = f0*al[lane] + f1*al[lane+32];
  float pr = f0*ar[lane] + f1*ar[lane+32];
  #pragma unroll
  for (int o = 16; o; o >>= 1) {
    pl += __shfl_xor_sync(0xffffffffu, pl, o);
    pr += __shfl_xor_sync(0xffffffffu, pr, o);
  }
  if (lane == 0) { g_el[row] = pl; g_er[row] = pr; }
}

// ---------------- CSR build ----------------
__global__ void zero_deg_k(int n){
  int i = blockIdx.x*blockDim.x + threadIdx.x;
  if (i < n) g_deg[i] = 0;
}
__global__ void hist_k(const int* __restrict__ dst, int e){
  int i = 4*(blockIdx.x*blockDim.x + threadIdx.x);
  if (i + 4 <= e) {
    int4 d = *(const int4*)(dst + i);
    int4 r;
    r.x = atomicAdd(&g_deg[d.x], 1);
    r.y = atomicAdd(&g_deg[d.y], 1);
    r.z = atomicAdd(&g_deg[d.z], 1);
    r.w = atomicAdd(&g_deg[d.w], 1);
    *(int4*)(g_rank + i) = r;
  } else {
    for (int j = i; j < e; ++j) g_rank[j] = atomicAdd(&g_deg[dst[j]], 1);
  }
}
__global__ void scan1_k(int n){
  __shared__ int ss[256];
  int per = (n + SCAN_BLOCKS - 1) / SCAN_BLOCKS;
  int b0 = blockIdx.x*per, b1 = min(b0+per, n);
  int s = 0;
  for (int i = b0 + threadIdx.x; i < b1; i += 256) s += g_deg[i];
  ss[threadIdx.x] = s;
  __syncthreads();
  for (int o = 128; o; o >>= 1) {
    if (threadIdx.x < o) ss[threadIdx.x] += ss[threadIdx.x + o];
    __syncthreads();
  }
  if (threadIdx.x == 0) g_bsum[blockIdx.x] = ss[0];
}
__global__ void scan3_k(int n, int e){
  __shared__ int ss[256];
  int part = 0;
  for (int i = threadIdx.x; i < blockIdx.x; i += 256) part += g_bsum[i];
  ss[threadIdx.x] = part;
  __syncthreads();
  for (int o = 128; o; o >>= 1) {
    if (threadIdx.x < o) ss[threadIdx.x] += ss[threadIdx.x + o];
    __syncthreads();
  }
  int base = ss[0];
  __syncthreads();

  int per = (n + SCAN_BLOCKS - 1) / SCAN_BLOCKS;
  int b0 = blockIdx.x*per, b1 = min(b0+per, n);
  int len = b1 - b0;
  int chunk = (len + 255) / 256;
  int t0 = b0 + threadIdx.x*chunk, t1 = min(t0 + chunk, b1);
  int s = 0;
  for (int i = t0; i < t1; ++i) s += g_deg[i];
  ss[threadIdx.x] = s;
  __syncthreads();
  for (int d = 1; d < 256; d <<= 1) {
    int t = (threadIdx.x >= d) ? ss[threadIdx.x-d] : 0;
    __syncthreads();
    ss[threadIdx.x] += t;
    __syncthreads();
  }
  int off = base + ss[threadIdx.x] - s;
  for (int i = t0; i < t1; ++i) { g_off[i] = off; off += g_deg[i]; }
  if (blockIdx.x == 0 && threadIdx.x == 0) g_off[n] = e;
}
__global__ void scatter2_k(const int* __restrict__ src, const int* __restrict__ dst, int e){
  int i = 4*(blockIdx.x*blockDim.x + threadIdx.x);
  if (i + 4 <= e) {
    int4 d = *(const int4*)(dst + i);
    int4 s = *(const int4*)(src + i);
    int4 r = *(const int4*)(g_rank + i);
    g_csr_src[g_off[d.x] + r.x] = s.x;
    g_csr_src[g_off[d.y] + r.y] = s.y;
    g_csr_src[g_off[d.z] + r.z] = s.z;
    g_csr_src[g_off[d.w] + r.w] = s.w;
  } else {
    for (int j = i; j < e; ++j) g_csr_src[g_off[dst[j]] + g_rank[j]] = src[j];
  }
}

// ---------------- fused per-layer edge kernel ----------------
__global__ void agg_k(int n, int layer){
  int tid = threadIdx.x, lane = tid & 31, warp = tid >> 5;
  int node = blockIdx.x * 8 + warp;
  if (node >= n) return;
  int beg = g_off[node], end = g_off[node+1];
  int deg = end - beg;
  float erd = g_er[node];

  if (deg <= 32) {
    int s = 0; float v = -1e30f;
    if (lane < deg) {
      s = g_csr_src[beg + lane];
      v = g_el[s] + erd;
      v = (v >= 0.f) ? v : 0.2f*v;
      if (layer > 0 && !g_mask[beg + lane]) v = -1e9f;
    }
    float m = v;
    #pragma unroll
    for (int o = 16; o; o >>= 1) m = fmaxf(m, __shfl_xor_sync(0xffffffffu, m, o));
    float a = (lane < deg) ? expf(v - m) : 0.f;
    float se = a;
    #pragma unroll
    for (int o = 16; o; o >>= 1) se += __shfl_xor_sync(0xffffffffu, se, o);
    float alpha = a / fmaxf(se, 1e-9f);
    if (layer == 0 && lane < deg) g_mask[beg + lane] = (alpha >= 0.01f) ? 1 : 0;
    if (alpha == 0.f) s = 0;

    int half = lane >> 4, q = lane & 15;
    const float* fb = g_feat + q*4;
    float4 acc = make_float4(0.f, 0.f, 0.f, 0.f);
    int npair = (deg + 1) >> 1;
    int p = 0;
    for (; p + 4 <= npair; p += 4) {
      int j0 = 2*p + half, j1 = j0 + 2, j2 = j0 + 4, j3 = j0 + 6;
      int s0 = __shfl_sync(0xffffffffu, s, j0);
      int s1 = __shfl_sync(0xffffffffu, s, j1);
      int s2 = __shfl_sync(0xffffffffu, s, j2);
      int s3 = __shfl_sync(0xffffffffu, s, j3);
      float a0 = __shfl_sync(0xffffffffu, alpha, j0);
      float a1 = __shfl_sync(0xffffffffu, alpha, j1);
      float a2 = __shfl_sync(0xffffffffu, alpha, j2);
      float a3 = __shfl_sync(0xffffffffu, alpha, j3);
      float4 f0 = *(const float4*)(fb + (size_t)s0*64);
      float4 f1 = *(const float4*)(fb + (size_t)s1*64);
      float4 f2 = *(const float4*)(fb + (size_t)s2*64);
      float4 f3 = *(const float4*)(fb + (size_t)s3*64);
      acc.x = fmaf(a0, f0.x, acc.x); acc.y = fmaf(a0, f0.y, acc.y);
      acc.z = fmaf(a0, f0.z, acc.z); acc.w = fmaf(a0, f0.w, acc.w);
      acc.x = fmaf(a1, f1.x, acc.x); acc.y = fmaf(a1, f1.y, acc.y);
      acc.z = fmaf(a1, f1.z, acc.z); acc.w = fmaf(a1, f1.w, acc.w);
      acc.x = fmaf(a2, f2.x, acc.x); acc.y = fmaf(a2, f2.y, acc.y);
      acc.z = fmaf(a2, f2.z, acc.z); acc.w = fmaf(a2, f2.w, acc.w);
      acc.x = fmaf(a3, f3.x, acc.x); acc.y = fmaf(a3, f3.y, acc.y);
      acc.z = fmaf(a3, f3.z, acc.z); acc.w = fmaf(a3, f3.w, acc.w);
    }
    for (; p < npair; ++p) {
      int j = 2*p + half;
      int sj = __shfl_sync(0xffffffffu, s, j);
      float aj = __shfl_sync(0xffffffffu, alpha, j);
      float4 f = *(const float4*)(fb + (size_t)sj*64);
      acc.x = fmaf(aj, f.x, acc.x); acc.y = fmaf(aj, f.y, acc.y);
      acc.z = fmaf(aj, f.z, acc.z); acc.w = fmaf(aj, f.w, acc.w);
    }
    acc.x += __shfl_xor_sync(0xffffffffu, acc.x, 16);
    acc.y += __shfl_xor_sync(0xffffffffu, acc.y, 16);
    acc.z += __shfl_xor_sync(0xffffffffu, acc.z, 16);
    acc.w += __shfl_xor_sync(0xffffffffu, acc.w, 16);
    if (half == 0) {
      float4 o;
      o.x = (acc.x > 0.f) ? acc.x : expm1f(acc.x);
      o.y = (acc.y > 0.f) ? acc.y : expm1f(acc.y);
      o.z = (acc.z > 0.f) ? acc.z : expm1f(acc.z);
      o.w = (acc.w > 0.f) ? acc.w : expm1f(acc.w);
      *(float4*)(g_h    + (size_t)node*64  + q*4) = o;
      *(float4*)(g_fcat + (size_t)node*256 + layer*64 + q*4) = o;
    }
  } else {
    float m = -1e30f;
    for (int j = beg + lane; j < end; j += 32) {
      int s = g_csr_src[j];
      float v = g_el[s] + erd;
      v = (v >= 0.f) ? v : 0.2f*v;
      if (layer > 0 && !g_mask[j]) v = -1e9f;
      g_aexp[j] = v;
      m = fmaxf(m, v);
    }
    #pragma unroll
    for (int o = 16; o; o >>= 1) m = fmaxf(m, __shfl_xor_sync(0xffffffffu, m, o));
    float se = 0.f;
    for (int j = beg + lane; j < end; j += 32) {
      float a = expf(g_aexp[j] - m);
      g_aexp[j] = a;
      se += a;
    }
    #pragma unroll
    for (int o = 16; o; o >>= 1) se += __shfl_xor_sync(0xffffffffu, se, o);
    float inv = 1.f / fmaxf(se, 1e-9f);
    __syncwarp();
    if (layer == 0) {
      for (int j = beg + lane; j < end; j += 32)
        g_mask[j] = (g_aexp[j]*inv >= 0.01f) ? 1 : 0;
    }
    float acc0 = 0.f, acc1 = 0.f;
    int j = beg;
    for (; j + 4 <= end; j += 4) {
      int s0 = g_csr_src[j], s1 = g_csr_src[j+1], s2 = g_csr_src[j+2], s3 = g_csr_src[j+3];
      float a0 = g_aexp[j]*inv,   a1 = g_aexp[j+1]*inv;
      float a2 = g_aexp[j+2]*inv, a3 = g_aexp[j+3]*inv;
      float2 f0 = *(const float2*)(g_feat + (size_t)s0*64 + 2*lane);
      float2 f1 = *(const float2*)(g_feat + (size_t)s1*64 + 2*lane);
      float2 f2 = *(const float2*)(g_feat + (size_t)s2*64 + 2*lane);
      float2 f3 = *(const float2*)(g_feat + (size_t)s3*64 + 2*lane);
      acc0 = fmaf(a0, f0.x, acc0); acc1 = fmaf(a0, f0.y, acc1);
      acc0 = fmaf(a1, f1.x, acc0); acc1 = fmaf(a1, f1.y, acc1);
      acc0 = fmaf(a2, f2.x, acc0); acc1 = fmaf(a2, f2.y, acc1);
      acc0 = fmaf(a3, f3.x, acc0); acc1 = fmaf(a3, f3.y, acc1);
    }
    for (; j < end; ++j) {
      int s = g_csr_src[j];
      float a = g_aexp[j]*inv;
      float2 f = *(const float2*)(g_feat + (size_t)s*64 + 2*lane);
      acc0 = fmaf(a, f.x, acc0); acc1 = fmaf(a, f.y, acc1);
    }
    float o0 = (acc0 > 0.f) ? acc0 : expm1f(acc0);
    float o1 = (acc1 > 0.f) ? acc1 : expm1f(acc1);
    g_h[(size_t)node*64 + 2*lane]     = o0;
    g_h[(size_t)node*64 + 2*lane + 1] = o1;
    g_fcat[(size_t)node*256 + layer*64 + 2*lane]     = o0;
    g_fcat[(size_t)node*256 + layer*64 + 2*lane + 1] = o1;
  }
}

// ---------------- final 64 -> 1 layer ----------------
__global__ void mlp2_k(const float* __restrict__ T, const float* __restrict__ W2,
                       const float* __restrict__ b2, float* __restrict__ out, int n){
  int tid = threadIdx.x, lane = tid & 31, warp = tid >> 5;
  int row = blockIdx.x * 8 + warp;
  if (row >= n) return;
  float s = T[(size_t)row*64 + lane]*W2[lane] + T[(size_t)row*64 + 32 + lane]*W2[lane+32];
  #pragma unroll
  for (int o = 16; o; o >>= 1) s += __shfl_xor_sync(0xffffffffu, s, o);
  if (lane == 0) out[row] = fmaxf(s + b2[0], 0.f);
}

// ---------------- launch ----------------
extern "C" void kernel_launch(void* const* d_in, const int* in_sizes, int n_in,
                              void* d_out, int out_size)
{
  const float* x       = (const float*)d_in[0];
  const int*   esrc    = (const int*)  d_in[1];
  const int*   edst    = (const int*)  d_in[2];
  const float* W_embed = (const float*)d_in[3];
  const float* W_gat   = (const float*)d_in[4];
  const float* a_l     = (const float*)d_in[5];
  const float* a_r     = (const float*)d_in[6];
  const float* W0      = (const float*)d_in[7];
  const float* b0      = (const float*)d_in[8];
  const float* W1      = (const float*)d_in[9];
  const float* b1      = (const float*)d_in[10];
  const float* W2      = (const float*)d_in[11];
  const float* b2      = (const float*)d_in[12];
  float* out = (float*)d_out;

  int n = in_sizes[0] / 128;
  int e = in_sizes[1];

  float *h_ptr, *feat_ptr, *fcat_ptr;
  cudaGetSymbolAddress((void**)&h_ptr,    g_h);
  cudaGetSymbolAddress((void**)&feat_ptr, g_feat);
  cudaGetSymbolAddress((void**)&fcat_ptr, g_fcat);

  int tiles = (n + 127) / 128;
  int gW = (n + 7) / 8;

  // CSR build (atomic-free scatter via ranks)
  zero_deg_k<<<(n + 255)/256, 256>>>(n);
  hist_k<<<((e+3)/4 + 255)/256, 256>>>(edst, e);
  scan1_k<<<SCAN_BLOCKS, 256>>>(n);
  scan3_k<<<SCAN_BLOCKS, 256>>>(n, e);
  scatter2_k<<<((e+3)/4 + 255)/256, 256>>>(esrc, edst, e);

  // embed
  gemm4_k<128, 1><<<tiles, 256>>>(x, W_embed, nullptr, h_ptr, n);

  for (int l = 0; l < 4; ++l) {
    gemm4_k<64, 0><<<tiles, 256>>>(h_ptr, W_gat + l*64*64, nullptr, feat_ptr, n);
    eler_k<<<gW, 256>>>(a_l + l*64, a_r + l*64, n);
    agg_k<<<gW, 256>>>(n, l);
  }

  // MLP head
  gemm4_k<256, 2><<<tiles, 256>>>(fcat_ptr, W0, b0, feat_ptr, n);
  gemm4_k<64,  2><<<tiles, 256>>>(feat_ptr, W1, b1, h_ptr, n);
  mlp2_k<<<gW, 256>>>(h_ptr, W2, b2, out, n);
}

// round 7
// speedup vs baseline: 1.1771x; 1.0464x over previous
#include <cuda_runtime.h>
#include <math.h>

#define N_NODES 50000
#define N_EDGES 800000
#define HID 64
#define SCAN_BLOCKS 128

// ---------------- scratch (device globals) ----------------
__device__ float g_h[N_NODES*HID];
__device__ float g_feat[N_NODES*HID];
__device__ float g_fcat[N_NODES*4*HID];
__device__ float g_el[N_NODES];
__device__ float g_er[N_NODES];
__device__ float g_aexp[N_EDGES];         // only used by the rare deg>32 path
__device__ unsigned char g_mask[N_EDGES];
__device__ int g_deg[N_NODES];
__device__ int g_off[N_NODES+1];
__device__ int g_rank[N_EDGES];
__device__ int g_csr_src[N_EDGES];
__device__ int g_bsum[SCAN_BLOCKS];

// ---------------- packed f32x2 helpers ----------------
__device__ __forceinline__ unsigned long long ffma2(unsigned long long a,
                                                    unsigned long long b,
                                                    unsigned long long c){
  unsigned long long d;
  asm("fma.rn.f32x2 %0, %1, %2, %3;" : "=l"(d) : "l"(a), "l"(b), "l"(c));
  return d;
}
__device__ __forceinline__ float2 unpackff(unsigned long long u){
  float2 f;
  asm("mov.b64 {%0, %1}, %2;" : "=f"(f.x), "=f"(f.y) : "l"(u));
  return f;
}

// ---------------- k-pair-packed GEMM with fused epilogues ----------------
// 256 threads; tile 128 rows x 64 cols; thread tile 8 rows x 4 cols.
// f32x2 lanes = (even k, odd k); epilogue folds .x+.y.
// ACT: 0=none, 1=tanh, 2=bias+relu
// MODE: 0=plain store; 1=store + el/er dots; 2=NO store, final dot W2 -> out[n]
template<int K, int ACT, int MODE>
__global__ void __launch_bounds__(256) gemm4_k(const float* __restrict__ A,
                        const float* __restrict__ W,
                        const float* __restrict__ bias, float* __restrict__ out, int n,
                        const float* __restrict__ al, const float* __restrict__ ar,
                        float* __restrict__ el, float* __restrict__ er,
                        const float* __restrict__ w2, const float* __restrict__ b2)
{
  __shared__ float As[128*64];
  __shared__ float Wt[64*64];
  int tid = threadIdx.x;
  int cg = tid & 15;            // cols cg*4 .. cg*4+3
  int rg = tid >> 4;            // rows rg*8 .. rg*8+7
  int row0 = blockIdx.x * 128;
  int mW = 2*cg;
  int mA = (rg & 1) << 1;

  unsigned long long acc[8][4];
  #pragma unroll
  for (int i = 0; i < 8; ++i)
    #pragma unroll
    for (int j = 0; j < 4; ++j) acc[i][j] = 0ull;

  for (int kc = 0; kc < K; kc += 64) {
    __syncthreads();
    #pragma unroll
    for (int j = 0; j < 8; ++j) {
      int idx = tid + 256*j;
      int r = idx >> 4, k0 = (idx & 15) * 4;
      float4 v = make_float4(0.f,0.f,0.f,0.f);
      int gr = row0 + r;
      if (gr < n) v = *(const float4*)(A + (size_t)gr*K + kc + k0);
      float4 s = ((r >> 3) & 1) ? make_float4(v.z, v.w, v.x, v.y) : v;
      *(float4*)&As[r*64 + k0] = s;
    }
    #pragma unroll
    for (int j = 0; j < 16; ++j) {
      int idx = tid + 256*j;
      int kr = idx >> 6;
      int c  = idx & 63;
      Wt[c*64 + (kr ^ (2*((c >> 2) & 15)))] = W[(size_t)(kc+kr)*64 + c];
    }
    __syncthreads();

    #pragma unroll 4
    for (int kp = 0; kp < 32; ++kp) {
      int k2 = 2*kp;
      unsigned long long a[8];
      #pragma unroll
      for (int i = 0; i < 8; ++i)
        a[i] = *(const unsigned long long*)&As[(rg*8+i)*64 + (k2 ^ mA)];
      unsigned long long w[4];
      #pragma unroll
      for (int j = 0; j < 4; ++j)
        w[j] = *(const unsigned long long*)&Wt[(cg*4+j)*64 + (k2 ^ mW)];
      #pragma unroll
      for (int i = 0; i < 8; ++i)
        #pragma unroll
        for (int j = 0; j < 4; ++j)
          acc[i][j] = ffma2(a[i], w[j], acc[i][j]);
    }
  }

  float4 bv = make_float4(0.f,0.f,0.f,0.f);
  if (ACT == 2) bv = *(const float4*)(bias + cg*4);
  float4 alv = make_float4(0.f,0.f,0.f,0.f), arv = alv, w2v = alv;
  float b2v = 0.f;
  if (MODE == 1) { alv = *(const float4*)(al + cg*4); arv = *(const float4*)(ar + cg*4); }
  if (MODE == 2) { w2v = *(const float4*)(w2 + cg*4); b2v = b2[0]; }

  #pragma unroll
  for (int i = 0; i < 8; ++i) {
    int r = row0 + rg*8 + i;
    float2 t0 = unpackff(acc[i][0]);
    float2 t1 = unpackff(acc[i][1]);
    float2 t2 = unpackff(acc[i][2]);
    float2 t3 = unpackff(acc[i][3]);
    float4 o = make_float4(t0.x+t0.y, t1.x+t1.y, t2.x+t2.y, t3.x+t3.y);
    if (ACT == 1) { o.x = tanhf(o.x); o.y = tanhf(o.y); o.z = tanhf(o.z); o.w = tanhf(o.w); }
    if (ACT == 2) {
      o.x = fmaxf(o.x + bv.x, 0.f); o.y = fmaxf(o.y + bv.y, 0.f);
      o.z = fmaxf(o.z + bv.z, 0.f); o.w = fmaxf(o.w + bv.w, 0.f);
    }
    if (MODE != 2 && r < n)
      *(float4*)(out + (size_t)r*64 + cg*4) = o;
    if (MODE == 1) {
      float pl = o.x*alv.x + o.y*alv.y + o.z*alv.z + o.w*alv.w;
      float pr = o.x*arv.x + o.y*arv.y + o.z*arv.z + o.w*arv.w;
      #pragma unroll
      for (int st = 1; st <= 8; st <<= 1) {
        pl += __shfl_xor_sync(0xffffffffu, pl, st);
        pr += __shfl_xor_sync(0xffffffffu, pr, st);
      }
      if (cg == 0 && r < n) { el[r] = pl; er[r] = pr; }
    }
    if (MODE == 2) {
      float p = o.x*w2v.x + o.y*w2v.y + o.z*w2v.z + o.w*w2v.w;
      #pragma unroll
      for (int st = 1; st <= 8; st <<= 1)
        p += __shfl_xor_sync(0xffffffffu, p, st);
      if (cg == 0 && r < n) out[r] = fmaxf(p + b2v, 0.f);
    }
  }
}

// ---------------- CSR build ----------------
__global__ void zero_deg_k(int n){
  int i = blockIdx.x*blockDim.x + threadIdx.x;
  if (i < n) g_deg[i] = 0;
}
__global__ void hist_k(const int* __restrict__ dst, int e){
  int i = 4*(blockIdx.x*blockDim.x + threadIdx.x);
  if (i + 4 <= e) {
    int4 d = *(const int4*)(dst + i);
    int4 r;
    r.x = atomicAdd(&g_deg[d.x], 1);
    r.y = atomicAdd(&g_deg[d.y], 1);
    r.z = atomicAdd(&g_deg[d.z], 1);
    r.w = atomicAdd(&g_deg[d.w], 1);
    *(int4*)(g_rank + i) = r;
  } else {
    for (int j = i; j < e; ++j) g_rank[j] = atomicAdd(&g_deg[dst[j]], 1);
  }
}
__global__ void scan1_k(int n){
  __shared__ int ss[256];
  int per = (n + SCAN_BLOCKS - 1) / SCAN_BLOCKS;
  int b0 = blockIdx.x*per, b1 = min(b0+per, n);
  int s = 0;
  for (int i = b0 + threadIdx.x; i < b1; i += 256) s += g_deg[i];
  ss[threadIdx.x] = s;
  __syncthreads();
  for (int o = 128; o; o >>= 1) {
    if (threadIdx.x < o) ss[threadIdx.x] += ss[threadIdx.x + o];
    __syncthreads();
  }
  if (threadIdx.x == 0) g_bsum[blockIdx.x] = ss[0];
}
__global__ void scan3_k(int n, int e){
  __shared__ int ss[256];
  int part = 0;
  for (int i = threadIdx.x; i < blockIdx.x; i += 256) part += g_bsum[i];
  ss[threadIdx.x] = part;
  __syncthreads();
  for (int o = 128; o; o >>= 1) {
    if (threadIdx.x < o) ss[threadIdx.x] += ss[threadIdx.x + o];
    __syncthreads();
  }
  int base = ss[0];
  __syncthreads();

  int per = (n + SCAN_BLOCKS - 1) / SCAN_BLOCKS;
  int b0 = blockIdx.x*per, b1 = min(b0+per, n);
  int len = b1 - b0;
  int chunk = (len + 255) / 256;
  int t0 = b0 + threadIdx.x*chunk, t1 = min(t0 + chunk, b1);
  int s = 0;
  for (int i = t0; i < t1; ++i) s += g_deg[i];
  ss[threadIdx.x] = s;
  __syncthreads();
  for (int d = 1; d < 256; d <<= 1) {
    int t = (threadIdx.x >= d) ? ss[threadIdx.x-d] : 0;
    __syncthreads();
    ss[threadIdx.x] += t;
    __syncthreads();
  }
  int off = base + ss[threadIdx.x] - s;
  for (int i = t0; i < t1; ++i) { g_off[i] = off; off += g_deg[i]; }
  if (blockIdx.x == 0 && threadIdx.x == 0) g_off[n] = e;
}
__global__ void scatter2_k(const int* __restrict__ src, const int* __restrict__ dst, int e){
  int i = 4*(blockIdx.x*blockDim.x + threadIdx.x);
  if (i + 4 <= e) {
    int4 d = *(const int4*)(dst + i);
    int4 s = *(const int4*)(src + i);
    int4 r = *(const int4*)(g_rank + i);
    g_csr_src[g_off[d.x] + r.x] = s.x;
    g_csr_src[g_off[d.y] + r.y] = s.y;
    g_csr_src[g_off[d.z] + r.z] = s.z;
    g_csr_src[g_off[d.w] + r.w] = s.w;
  } else {
    for (int j = i; j < e; ++j) g_csr_src[g_off[dst[j]] + g_rank[j]] = src[j];
  }
}

// ---------------- fused per-layer edge kernel (512 threads, 16 nodes/block) ----------------
__global__ void __launch_bounds__(512) agg_k(int n, int layer){
  int tid = threadIdx.x, lane = tid & 31, warp = tid >> 5;
  int node = blockIdx.x * 16 + warp;
  if (node >= n) return;
  int beg = g_off[node], end = g_off[node+1];
  int deg = end - beg;
  float erd = g_er[node];

  if (deg <= 32) {
    int s = 0; float v = -1e30f;
    if (lane < deg) {
      s = g_csr_src[beg + lane];
      v = g_el[s] + erd;
      v = (v >= 0.f) ? v : 0.2f*v;
      if (layer > 0 && !g_mask[beg + lane]) v = -1e9f;
    }
    float m = v;
    #pragma unroll
    for (int o = 16; o; o >>= 1) m = fmaxf(m, __shfl_xor_sync(0xffffffffu, m, o));
    float a = (lane < deg) ? expf(v - m) : 0.f;
    float se = a;
    #pragma unroll
    for (int o = 16; o; o >>= 1) se += __shfl_xor_sync(0xffffffffu, se, o);
    float alpha = a / fmaxf(se, 1e-9f);
    if (layer == 0 && lane < deg) g_mask[beg + lane] = (alpha >= 0.01f) ? 1 : 0;
    if (alpha == 0.f) s = 0;

    int half = lane >> 4, q = lane & 15;
    const float* fb = g_feat + q*4;
    float4 acc = make_float4(0.f, 0.f, 0.f, 0.f);
    int npair = (deg + 1) >> 1;
    int p = 0;
    for (; p + 4 <= npair; p += 4) {
      int j0 = 2*p + half, j1 = j0 + 2, j2 = j0 + 4, j3 = j0 + 6;
      int s0 = __shfl_sync(0xffffffffu, s, j0);
      int s1 = __shfl_sync(0xffffffffu, s, j1);
      int s2 = __shfl_sync(0xffffffffu, s, j2);
      int s3 = __shfl_sync(0xffffffffu, s, j3);
      float a0 = __shfl_sync(0xffffffffu, alpha, j0);
      float a1 = __shfl_sync(0xffffffffu, alpha, j1);
      float a2 = __shfl_sync(0xffffffffu, alpha, j2);
      float a3 = __shfl_sync(0xffffffffu, alpha, j3);
      float4 f0 = *(const float4*)(fb + (size_t)s0*64);
      float4 f1 = *(const float4*)(fb + (size_t)s1*64);
      float4 f2 = *(const float4*)(fb + (size_t)s2*64);
      float4 f3 = *(const float4*)(fb + (size_t)s3*64);
      acc.x = fmaf(a0, f0.x, acc.x); acc.y = fmaf(a0, f0.y, acc.y);
      acc.z = fmaf(a0, f0.z, acc.z); acc.w = fmaf(a0, f0.w, acc.w);
      acc.x = fmaf(a1, f1.x, acc.x); acc.y = fmaf(a1, f1.y, acc.y);
      acc.z = fmaf(a1, f1.z, acc.z); acc.w = fmaf(a1, f1.w, acc.w);
      acc.x = fmaf(a2, f2.x, acc.x); acc.y = fmaf(a2, f2.y, acc.y);
      acc.z = fmaf(a2, f2.z, acc.z); acc.w = fmaf(a2, f2.w, acc.w);
      acc.x = fmaf(a3, f3.x, acc.x); acc.y = fmaf(a3, f3.y, acc.y);
      acc.z = fmaf(a3, f3.z, acc.z); acc.w = fmaf(a3, f3.w, acc.w);
    }
    for (; p < npair; ++p) {
      int j = 2*p + half;
      int sj = __shfl_sync(0xffffffffu, s, j);
      float aj = __shfl_sync(0xffffffffu, alpha, j);
      float4 f = *(const float4*)(fb + (size_t)sj*64);
      acc.x = fmaf(aj, f.x, acc.x); acc.y = fmaf(aj, f.y, acc.y);
      acc.z = fmaf(aj, f.z, acc.z); acc.w = fmaf(aj, f.w, acc.w);
    }
    acc.x += __shfl_xor_sync(0xffffffffu, acc.x, 16);
    acc.y += __shfl_xor_sync(0xffffffffu, acc.y, 16);
    acc.z += __shfl_xor_sync(0xffffffffu, acc.z, 16);
    acc.w += __shfl_xor_sync(0xffffffffu, acc.w, 16);
    if (half == 0) {
      float4 o;
      o.x = (acc.x > 0.f) ? acc.x : expm1f(acc.x);
      o.y = (acc.y > 0.f) ? acc.y : expm1f(acc.y);
      o.z = (acc.z > 0.f) ? acc.z : expm1f(acc.z);
      o.w = (acc.w > 0.f) ? acc.w : expm1f(acc.w);
      *(float4*)(g_h    + (size_t)node*64  + q*4) = o;
      *(float4*)(g_fcat + (size_t)node*256 + layer*64 + q*4) = o;
    }
  } else {
    float m = -1e30f;
    for (int j = beg + lane; j < end; j += 32) {
      int s = g_csr_src[j];
      float v = g_el[s] + erd;
      v = (v >= 0.f) ? v : 0.2f*v;
      if (layer > 0 && !g_mask[j]) v = -1e9f;
      g_aexp[j] = v;
      m = fmaxf(m, v);
    }
    #pragma unroll
    for (int o = 16; o; o >>= 1) m = fmaxf(m, __shfl_xor_sync(0xffffffffu, m, o));
    float se = 0.f;
    for (int j = beg + lane; j < end; j += 32) {
      float a = expf(g_aexp[j] - m);
      g_aexp[j] = a;
      se += a;
    }
    #pragma unroll
    for (int o = 16; o; o >>= 1) se += __shfl_xor_sync(0xffffffffu, se, o);
    float inv = 1.f / fmaxf(se, 1e-9f);
    __syncwarp();
    if (layer == 0) {
      for (int j = beg + lane; j < end; j += 32)
        g_mask[j] = (g_aexp[j]*inv >= 0.01f) ? 1 : 0;
    }
    float acc0 = 0.f, acc1 = 0.f;
    int j = beg;
    for (; j + 4 <= end; j += 4) {
      int s0 = g_csr_src[j], s1 = g_csr_src[j+1], s2 = g_csr_src[j+2], s3 = g_csr_src[j+3];
      float a0 = g_aexp[j]*inv,   a1 = g_aexp[j+1]*inv;
      float a2 = g_aexp[j+2]*inv, a3 = g_aexp[j+3]*inv;
      float2 f0 = *(const float2*)(g_feat + (size_t)s0*64 + 2*lane);
      float2 f1 = *(const float2*)(g_feat + (size_t)s1*64 + 2*lane);
      float2 f2 = *(const float2*)(g_feat + (size_t)s2*64 + 2*lane);
      float2 f3 = *(const float2*)(g_feat + (size_t)s3*64 + 2*lane);
      acc0 = fmaf(a0, f0.x, acc0); acc1 = fmaf(a0, f0.y, acc1);
      acc0 = fmaf(a1, f1.x, acc0); acc1 = fmaf(a1, f1.y, acc1);
      acc0 = fmaf(a2, f2.x, acc0); acc1 = fmaf(a2, f2.y, acc1);
      acc0 = fmaf(a3, f3.x, acc0); acc1 = fmaf(a3, f3.y, acc1);
    }
    for (; j < end; ++j) {
      int s = g_csr_src[j];
      float a = g_aexp[j]*inv;
      float2 f = *(const float2*)(g_feat + (size_t)s*64 + 2*lane);
      acc0 = fmaf(a, f.x, acc0); acc1 = fmaf(a, f.y, acc1);
    }
    float o0 = (acc0 > 0.f) ? acc0 : expm1f(acc0);
    float o1 = (acc1 > 0.f) ? acc1 : expm1f(acc1);
    g_h[(size_t)node*64 + 2*lane]     = o0;
    g_h[(size_t)node*64 + 2*lane + 1] = o1;
    g_fcat[(size_t)node*256 + layer*64 + 2*lane]     = o0;
    g_fcat[(size_t)node*256 + layer*64 + 2*lane + 1] = o1;
  }
}

// ---------------- launch ----------------
extern "C" void kernel_launch(void* const* d_in, const int* in_sizes, int n_in,
                              void* d_out, int out_size)
{
  const float* x       = (const float*)d_in[0];
  const int*   esrc    = (const int*)  d_in[1];
  const int*   edst    = (const int*)  d_in[2];
  const float* W_embed = (const float*)d_in[3];
  const float* W_gat   = (const float*)d_in[4];
  const float* a_l     = (const float*)d_in[5];
  const float* a_r     = (const float*)d_in[6];
  const float* W0      = (const float*)d_in[7];
  const float* b0      = (const float*)d_in[8];
  const float* W1      = (const float*)d_in[9];
  const float* b1      = (const float*)d_in[10];
  const float* W2      = (const float*)d_in[11];
  const float* b2      = (const float*)d_in[12];
  float* out = (float*)d_out;

  int n = in_sizes[0] / 128;
  int e = in_sizes[1];

  float *h_ptr, *feat_ptr, *fcat_ptr, *el_ptr, *er_ptr;
  cudaGetSymbolAddress((void**)&h_ptr,    g_h);
  cudaGetSymbolAddress((void**)&feat_ptr, g_feat);
  cudaGetSymbolAddress((void**)&fcat_ptr, g_fcat);
  cudaGetSymbolAddress((void**)&el_ptr,   g_el);
  cudaGetSymbolAddress((void**)&er_ptr,   g_er);

  int tiles = (n + 127) / 128;

  // CSR build (atomic-free scatter via ranks)
  zero_deg_k<<<(n + 255)/256, 256>>>(n);
  hist_k<<<((e+3)/4 + 255)/256, 256>>>(edst, e);
  scan1_k<<<SCAN_BLOCKS, 256>>>(n);
  scan3_k<<<SCAN_BLOCKS, 256>>>(n, e);
  scatter2_k<<<((e+3)/4 + 255)/256, 256>>>(esrc, edst, e);

  // embed: h = tanh(x @ W_embed)
  gemm4_k<128, 1, 0><<<tiles, 256>>>(x, W_embed, nullptr, h_ptr, n,
                                     nullptr, nullptr, nullptr, nullptr, nullptr, nullptr);

  for (int l = 0; l < 4; ++l) {
    gemm4_k<64, 0, 1><<<tiles, 256>>>(h_ptr, W_gat + l*64*64, nullptr, feat_ptr, n,
                                      a_l + l*64, a_r + l*64, el_ptr, er_ptr,
                                      nullptr, nullptr);
    agg_k<<<(n + 15)/16, 512>>>(n, l);
  }

  // MLP head: fcat -> 64 (relu) -> [64 (relu) -> 1 (relu), fused]
  gemm4_k<256, 2, 0><<<tiles, 256>>>(fcat_ptr, W0, b0, feat_ptr, n,
                                     nullptr, nullptr, nullptr, nullptr, nullptr, nullptr);
  gemm4_k<64, 2, 2><<<tiles, 256>>>(feat_ptr, W1, b1, out, n,
                                    nullptr, nullptr, nullptr, nullptr, W2, b2);
}

// round 8
// speedup vs baseline: 1.2314x; 1.0461x over previous
#include <cuda_runtime.h>
#include <math.h>

#define N_NODES 50000
#define N_EDGES 800000
#define HID 64
#define ELLW 64

// ---------------- scratch (device globals) ----------------
__device__ float g_h[N_NODES*HID];          // embed output only
__device__ float g_feat[N_NODES*HID];       // conv GEMM out / MLP tmp
__device__ float g_fcat[N_NODES*4*HID];     // concat buffer [N,256]; agg writes slots
__device__ float g_el[N_NODES];
__device__ float g_er[N_NODES];
__device__ unsigned char g_mask[N_NODES*ELLW];
__device__ int g_deg[N_NODES];
__device__ int g_ell[N_NODES*ELLW];

// ---------------- packed f32x2 helpers ----------------
__device__ __forceinline__ unsigned long long ffma2(unsigned long long a,
                                                    unsigned long long b,
                                                    unsigned long long c){
  unsigned long long d;
  asm("fma.rn.f32x2 %0, %1, %2, %3;" : "=l"(d) : "l"(a), "l"(b), "l"(c));
  return d;
}
__device__ __forceinline__ float2 unpackff(unsigned long long u){
  float2 f;
  asm("mov.b64 {%0, %1}, %2;" : "=f"(f.x), "=f"(f.y) : "l"(u));
  return f;
}

// ---------------- k-pair-packed GEMM with fused epilogues ----------------
// 256 threads; tile 128 rows x 64 cols; thread tile 8 rows x 4 cols.
// ACT: 0=none, 1=tanh, 2=bias+relu
// MODE: 0=plain store; 1=store + el/er dots; 2=NO store, final dot W2 -> out[n]
template<int K, int ACT, int MODE>
__global__ void __launch_bounds__(256) gemm4_k(const float* __restrict__ A, int lda,
                        const float* __restrict__ W,
                        const float* __restrict__ bias, float* __restrict__ out, int n,
                        const float* __restrict__ al, const float* __restrict__ ar,
                        float* __restrict__ el, float* __restrict__ er,
                        const float* __restrict__ w2, const float* __restrict__ b2)
{
  __shared__ float As[128*64];
  __shared__ float Wt[64*64];
  int tid = threadIdx.x;
  int cg = tid & 15;
  int rg = tid >> 4;
  int row0 = blockIdx.x * 128;
  int mW = 2*cg;
  int mA = (rg & 1) << 1;

  unsigned long long acc[8][4];
  #pragma unroll
  for (int i = 0; i < 8; ++i)
    #pragma unroll
    for (int j = 0; j < 4; ++j) acc[i][j] = 0ull;

  for (int kc = 0; kc < K; kc += 64) {
    __syncthreads();
    #pragma unroll
    for (int j = 0; j < 8; ++j) {
      int idx = tid + 256*j;
      int r = idx >> 4, k0 = (idx & 15) * 4;
      float4 v = make_float4(0.f,0.f,0.f,0.f);
      int gr = row0 + r;
      if (gr < n) v = *(const float4*)(A + (size_t)gr*lda + kc + k0);
      float4 s = ((r >> 3) & 1) ? make_float4(v.z, v.w, v.x, v.y) : v;
      *(float4*)&As[r*64 + k0] = s;
    }
    #pragma unroll
    for (int j = 0; j < 16; ++j) {
      int idx = tid + 256*j;
      int kr = idx >> 6;
      int c  = idx & 63;
      Wt[c*64 + (kr ^ (2*((c >> 2) & 15)))] = W[(size_t)(kc+kr)*64 + c];
    }
    __syncthreads();

    #pragma unroll 4
    for (int kp = 0; kp < 32; ++kp) {
      int k2 = 2*kp;
      unsigned long long a[8];
      #pragma unroll
      for (int i = 0; i < 8; ++i)
        a[i] = *(const unsigned long long*)&As[(rg*8+i)*64 + (k2 ^ mA)];
      unsigned long long w[4];
      #pragma unroll
      for (int j = 0; j < 4; ++j)
        w[j] = *(const unsigned long long*)&Wt[(cg*4+j)*64 + (k2 ^ mW)];
      #pragma unroll
      for (int i = 0; i < 8; ++i)
        #pragma unroll
        for (int j = 0; j < 4; ++j)
          acc[i][j] = ffma2(a[i], w[j], acc[i][j]);
    }
  }

  float4 bv = make_float4(0.f,0.f,0.f,0.f);
  if (ACT == 2) bv = *(const float4*)(bias + cg*4);
  float4 alv = make_float4(0.f,0.f,0.f,0.f), arv = alv, w2v = alv;
  float b2v = 0.f;
  if (MODE == 1) { alv = *(const float4*)(al + cg*4); arv = *(const float4*)(ar + cg*4); }
  if (MODE == 2) { w2v = *(const float4*)(w2 + cg*4); b2v = b2[0]; }

  #pragma unroll
  for (int i = 0; i < 8; ++i) {
    int r = row0 + rg*8 + i;
    float2 t0 = unpackff(acc[i][0]);
    float2 t1 = unpackff(acc[i][1]);
    float2 t2 = unpackff(acc[i][2]);
    float2 t3 = unpackff(acc[i][3]);
    float4 o = make_float4(t0.x+t0.y, t1.x+t1.y, t2.x+t2.y, t3.x+t3.y);
    if (ACT == 1) { o.x = tanhf(o.x); o.y = tanhf(o.y); o.z = tanhf(o.z); o.w = tanhf(o.w); }
    if (ACT == 2) {
      o.x = fmaxf(o.x + bv.x, 0.f); o.y = fmaxf(o.y + bv.y, 0.f);
      o.z = fmaxf(o.z + bv.z, 0.f); o.w = fmaxf(o.w + bv.w, 0.f);
    }
    if (MODE != 2 && r < n)
      *(float4*)(out + (size_t)r*64 + cg*4) = o;
    if (MODE == 1) {
      float pl = o.x*alv.x + o.y*alv.y + o.z*alv.z + o.w*alv.w;
      float pr = o.x*arv.x + o.y*arv.y + o.z*arv.z + o.w*arv.w;
      #pragma unroll
      for (int st = 1; st <= 8; st <<= 1) {
        pl += __shfl_xor_sync(0xffffffffu, pl, st);
        pr += __shfl_xor_sync(0xffffffffu, pr, st);
      }
      if (cg == 0 && r < n) { el[r] = pl; er[r] = pr; }
    }
    if (MODE == 2) {
      float p = o.x*w2v.x + o.y*w2v.y + o.z*w2v.z + o.w*w2v.w;
      #pragma unroll
      for (int st = 1; st <= 8; st <<= 1)
        p += __shfl_xor_sync(0xffffffffu, p, st);
      if (cg == 0 && r < n) out[r] = fmaxf(p + b2v, 0.f);
    }
  }
}

// ---------------- ELL build: zero degrees, then fused hist+scatter ----------------
__global__ void zero_deg_k(int n){
  int i = blockIdx.x*blockDim.x + threadIdx.x;
  if (i < n) g_deg[i] = 0;
}
__global__ void build_k(const int* __restrict__ src, const int* __restrict__ dst, int e){
  int i = 4*(blockIdx.x*blockDim.x + threadIdx.x);
  if (i + 4 <= e) {
    int4 d = *(const int4*)(dst + i);
    int4 s = *(const int4*)(src + i);
    int r0 = atomicAdd(&g_deg[d.x], 1);
    int r1 = atomicAdd(&g_deg[d.y], 1);
    int r2 = atomicAdd(&g_deg[d.z], 1);
    int r3 = atomicAdd(&g_deg[d.w], 1);
    g_ell[d.x*ELLW + r0] = s.x;
    g_ell[d.y*ELLW + r1] = s.y;
    g_ell[d.z*ELLW + r2] = s.z;
    g_ell[d.w*ELLW + r3] = s.w;
  } else {
    for (int j = i; j < e; ++j) {
      int r = atomicAdd(&g_deg[dst[j]], 1);
      g_ell[dst[j]*ELLW + r] = src[j];
    }
  }
}

// ---------------- fused per-layer edge kernel (512 threads, 16 nodes/block) ----------------
__global__ void __launch_bounds__(512) agg_k(int n, int layer){
  int tid = threadIdx.x, lane = tid & 31, warp = tid >> 5;
  int node = blockIdx.x * 16 + warp;
  if (node >= n) return;
  int base = node * ELLW;
  int deg = g_deg[node];
  float erd = g_er[node];

  int half = lane >> 4, q = lane & 15;
  const float* fb = g_feat + q*4;
  float4 acc = make_float4(0.f, 0.f, 0.f, 0.f);

  if (deg <= 32) {
    int s = 0; float v = -1e30f;
    if (lane < deg) {
      s = g_ell[base + lane];
      v = g_el[s] + erd;
      v = (v >= 0.f) ? v : 0.2f*v;
      if (layer > 0 && !g_mask[base + lane]) v = -1e9f;
    }
    float m = v;
    #pragma unroll
    for (int o = 16; o; o >>= 1) m = fmaxf(m, __shfl_xor_sync(0xffffffffu, m, o));
    float a = (lane < deg) ? expf(v - m) : 0.f;
    float se = a;
    #pragma unroll
    for (int o = 16; o; o >>= 1) se += __shfl_xor_sync(0xffffffffu, se, o);
    float alpha = a / fmaxf(se, 1e-9f);
    if (layer == 0 && lane < deg) g_mask[base + lane] = (alpha >= 0.01f) ? 1 : 0;
    if (alpha == 0.f) s = 0;

    int npair = (deg + 1) >> 1;
    int p = 0;
    for (; p + 4 <= npair; p += 4) {
      int j0 = 2*p + half, j1 = j0 + 2, j2 = j0 + 4, j3 = j0 + 6;
      int s0 = __shfl_sync(0xffffffffu, s, j0);
      int s1 = __shfl_sync(0xffffffffu, s, j1);
      int s2 = __shfl_sync(0xffffffffu, s, j2);
      int s3 = __shfl_sync(0xffffffffu, s, j3);
      float a0 = __shfl_sync(0xffffffffu, alpha, j0);
      float a1 = __shfl_sync(0xffffffffu, alpha, j1);
      float a2 = __shfl_sync(0xffffffffu, alpha, j2);
      float a3 = __shfl_sync(0xffffffffu, alpha, j3);
      float4 f0 = *(const float4*)(fb + (size_t)s0*64);
      float4 f1 = *(const float4*)(fb + (size_t)s1*64);
      float4 f2 = *(const float4*)(fb + (size_t)s2*64);
      float4 f3 = *(const float4*)(fb + (size_t)s3*64);
      acc.x = fmaf(a0, f0.x, acc.x); acc.y = fmaf(a0, f0.y, acc.y);
      acc.z = fmaf(a0, f0.z, acc.z); acc.w = fmaf(a0, f0.w, acc.w);
      acc.x = fmaf(a1, f1.x, acc.x); acc.y = fmaf(a1, f1.y, acc.y);
      acc.z = fmaf(a1, f1.z, acc.z); acc.w = fmaf(a1, f1.w, acc.w);
      acc.x = fmaf(a2, f2.x, acc.x); acc.y = fmaf(a2, f2.y, acc.y);
      acc.z = fmaf(a2, f2.z, acc.z); acc.w = fmaf(a2, f2.w, acc.w);
      acc.x = fmaf(a3, f3.x, acc.x); acc.y = fmaf(a3, f3.y, acc.y);
      acc.z = fmaf(a3, f3.z, acc.z); acc.w = fmaf(a3, f3.w, acc.w);
    }
    for (; p < npair; ++p) {
      int j = 2*p + half;
      int sj = __shfl_sync(0xffffffffu, s, j);
      float aj = __shfl_sync(0xffffffffu, alpha, j);
      float4 f = *(const float4*)(fb + (size_t)sj*64);
      acc.x = fmaf(aj, f.x, acc.x); acc.y = fmaf(aj, f.y, acc.y);
      acc.z = fmaf(aj, f.z, acc.z); acc.w = fmaf(aj, f.w, acc.w);
    }
  } else {
    // deg in (32, 64]: 2 edges per lane, register-resident (ultra-rare)
    int dd = (deg <= ELLW) ? deg : ELLW;
    int s0 = 0, s1 = 0; float v0 = -1e30f, v1 = -1e30f;
    if (lane < dd) {
      s0 = g_ell[base + lane];
      v0 = g_el[s0] + erd;
      v0 = (v0 >= 0.f) ? v0 : 0.2f*v0;
      if (layer > 0 && !g_mask[base + lane]) v0 = -1e9f;
    }
    if (lane + 32 < dd) {
      s1 = g_ell[base + lane + 32];
      v1 = g_el[s1] + erd;
      v1 = (v1 >= 0.f) ? v1 : 0.2f*v1;
      if (layer > 0 && !g_mask[base + lane + 32]) v1 = -1e9f;
    }
    float m = fmaxf(v0, v1);
    #pragma unroll
    for (int o = 16; o; o >>= 1) m = fmaxf(m, __shfl_xor_sync(0xffffffffu, m, o));
    float a0 = (lane < dd) ? expf(v0 - m) : 0.f;
    float a1 = (lane + 32 < dd) ? expf(v1 - m) : 0.f;
    float se = a0 + a1;
    #pragma unroll
    for (int o = 16; o; o >>= 1) se += __shfl_xor_sync(0xffffffffu, se, o);
    float inv = 1.f / fmaxf(se, 1e-9f);
    float al0 = a0 * inv, al1 = a1 * inv;
    if (layer == 0) {
      if (lane < dd)      g_mask[base + lane]      = (al0 >= 0.01f) ? 1 : 0;
      if (lane + 32 < dd) g_mask[base + lane + 32] = (al1 >= 0.01f) ? 1 : 0;
    }
    if (al0 == 0.f) s0 = 0;
    if (al1 == 0.f) s1 = 0;

    int npair = (dd + 1) >> 1;
    for (int p = 0; p < npair; ++p) {
      int j = 2*p + half;
      int sa = __shfl_sync(0xffffffffu, s0, j & 31);
      int sb = __shfl_sync(0xffffffffu, s1, j & 31);
      float aa = __shfl_sync(0xffffffffu, al0, j & 31);
      float ab = __shfl_sync(0xffffffffu, al1, j & 31);
      int sj   = (j < 32) ? sa : sb;
      float aj = (j < 32) ? aa : ab;
      if (j < dd) {
        float4 f = *(const float4*)(fb + (size_t)sj*64);
        acc.x = fmaf(aj, f.x, acc.x); acc.y = fmaf(aj, f.y, acc.y);
        acc.z = fmaf(aj, f.z, acc.z); acc.w = fmaf(aj, f.w, acc.w);
      }
    }
  }

  acc.x += __shfl_xor_sync(0xffffffffu, acc.x, 16);
  acc.y += __shfl_xor_sync(0xffffffffu, acc.y, 16);
  acc.z += __shfl_xor_sync(0xffffffffu, acc.z, 16);
  acc.w += __shfl_xor_sync(0xffffffffu, acc.w, 16);
  if (half == 0) {
    float4 o;
    o.x = (acc.x > 0.f) ? acc.x : expm1f(acc.x);
    o.y = (acc.y > 0.f) ? acc.y : expm1f(acc.y);
    o.z = (acc.z > 0.f) ? acc.z : expm1f(acc.z);
    o.w = (acc.w > 0.f) ? acc.w : expm1f(acc.w);
    *(float4*)(g_fcat + (size_t)node*256 + layer*64 + q*4) = o;
  }
}

// ---------------- launch ----------------
extern "C" void kernel_launch(void* const* d_in, const int* in_sizes, int n_in,
                              void* d_out, int out_size)
{
  const float* x       = (const float*)d_in[0];
  const int*   esrc    = (const int*)  d_in[1];
  const int*   edst    = (const int*)  d_in[2];
  const float* W_embed = (const float*)d_in[3];
  const float* W_gat   = (const float*)d_in[4];
  const float* a_l     = (const float*)d_in[5];
  const float* a_r     = (const float*)d_in[6];
  const float* W0      = (const float*)d_in[7];
  const float* b0      = (const float*)d_in[8];
  const float* W1      = (const float*)d_in[9];
  const float* b1      = (const float*)d_in[10];
  const float* W2      = (const float*)d_in[11];
  const float* b2      = (const float*)d_in[12];
  float* out = (float*)d_out;

  int n = in_sizes[0] / 128;
  int e = in_sizes[1];

  float *h_ptr, *feat_ptr, *fcat_ptr, *el_ptr, *er_ptr;
  cudaGetSymbolAddress((void**)&h_ptr,    g_h);
  cudaGetSymbolAddress((void**)&feat_ptr, g_feat);
  cudaGetSymbolAddress((void**)&fcat_ptr, g_fcat);
  cudaGetSymbolAddress((void**)&el_ptr,   g_el);
  cudaGetSymbolAddress((void**)&er_ptr,   g_er);

  int tiles = (n + 127) / 128;

  // ELL build (2 launches; rank from hist atomicAdd is the ELL slot)
  zero_deg_k<<<(n + 255)/256, 256>>>(n);
  build_k<<<((e+3)/4 + 255)/256, 256>>>(esrc, edst, e);

  // embed: h = tanh(x @ W_embed)
  gemm4_k<128, 1, 0><<<tiles, 256>>>(x, 128, W_embed, nullptr, h_ptr, n,
                                     nullptr, nullptr, nullptr, nullptr, nullptr, nullptr);

  for (int l = 0; l < 4; ++l) {
    const float* Ain = (l == 0) ? h_ptr : (fcat_ptr + (l-1)*64);
    int lda = (l == 0) ? 64 : 256;
    gemm4_k<64, 0, 1><<<tiles, 256>>>(Ain, lda, W_gat + l*64*64, nullptr, feat_ptr, n,
                                      a_l + l*64, a_r + l*64, el_ptr, er_ptr,
                                      nullptr, nullptr);
    agg_k<<<(n + 15)/16, 512>>>(n, l);
  }

  // MLP head: fcat -> 64 (relu) -> [64 (relu) -> 1 (relu), fused]
  gemm4_k<256, 2, 0><<<tiles, 256>>>(fcat_ptr, 256, W0, b0, feat_ptr, n,
                                     nullptr, nullptr, nullptr, nullptr, nullptr, nullptr);
  gemm4_k<64, 2, 2><<<tiles, 256>>>(feat_ptr, 64, W1, b1, out, n,
                                    nullptr, nullptr, nullptr, nullptr, W2, b2);
}